// round 16
// baseline (speedup 1.0000x reference)
#include <cuda_runtime.h>
#include <cuda_fp16.h>
#include <cstdint>

#define NV 10000
#define NB 16
#define NR 8
#define NC 64
#define NU 64
#define ROWS 128
#define NTHREADS 512
#define NROWS_TOT (NB * NV)          // 160000

// ---- device-global scratch (zero-init; row NROWS_TOT stays zero for m=-1) ----
__device__ __align__(16) __half    g_nodes_h[(NROWS_TOT + 8) * NC];   // ~20.5MB
__device__ __align__(16) unsigned  g_kern_pair[NR * 32 * 64];         // paired f16

// ---- smem layout (bytes) ----
#define A_BUF 16384                  // 128 rows * 128B f16, XOR-swizzled
#define B_BUF 9216                   // 32 p-rows * 288B (72 words, conflict-free)
#define OFF_A 0
#define OFF_B (2 * A_BUF)            // 32768
#define SMEM_BYTES (OFF_B + 2 * B_BUF)   // 51200 -> 2 CTA/SM

// ---------------- helpers ----------------
__device__ __forceinline__ unsigned cvta_smem(const void* p) {
    unsigned r;
    asm("{ .reg .u64 t; cvta.to.shared.u64 t, %1; cvt.u32.u64 %0, t; }"
        : "=r"(r) : "l"(p));
    return r;
}
__device__ __forceinline__ void cpasync16(unsigned dst, const void* src) {
    asm volatile("cp.async.cg.shared.global [%0], [%1], 16;" :: "r"(dst), "l"(src));
}
#define CP_COMMIT() asm volatile("cp.async.commit_group;" ::: "memory")
#define CP_WAIT(n)  asm volatile("cp.async.wait_group %0;" :: "n"(n) : "memory")

__device__ __forceinline__ unsigned f16x2(float hi, float lo) {
    unsigned d;
    asm("cvt.rn.f16x2.f32 %0, %1, %2;" : "=r"(d) : "f"(hi), "f"(lo));
    return d;
}
__device__ __forceinline__ void ldsm_x4(unsigned addr, unsigned& r0, unsigned& r1,
                                        unsigned& r2, unsigned& r3) {
    asm volatile("ldmatrix.sync.aligned.m8n8.x4.shared.b16 {%0,%1,%2,%3}, [%4];"
                 : "=r"(r0), "=r"(r1), "=r"(r2), "=r"(r3) : "r"(addr));
}
__device__ __forceinline__ void mma_f16(float& d0, float& d1, float& d2, float& d3,
                                        unsigned a0, unsigned a1, unsigned a2, unsigned a3,
                                        unsigned b0, unsigned b1) {
    asm volatile("mma.sync.aligned.m16n8k16.row.col.f32.f16.f16.f32 "
                 "{%0,%1,%2,%3}, {%4,%5,%6,%7}, {%8,%9}, {%0,%1,%2,%3};"
                 : "+f"(d0), "+f"(d1), "+f"(d2), "+f"(d3)
                 : "r"(a0), "r"(a1), "r"(a2), "r"(a3), "r"(b0), "r"(b1));
}

// ---------------- merged pre-pass kernel ----------------
__global__ void conv_all(const float* __restrict__ nodes,
                         const float* __restrict__ kern) {
    if (blockIdx.x < 2048) {
        // nodes: 160000*64 fp32 -> fp16; 2 float4 per iter, 16B stores
        const int total = NROWS_TOT * NC / 8;      // float4-pair count (1.28M)
        const float4* src = (const float4*)nodes;
        uint4* dst = (uint4*)g_nodes_h;
        for (int i = blockIdx.x * blockDim.x + threadIdx.x; i < total;
             i += 2048 * blockDim.x) {
            float4 v0 = src[2 * i];
            float4 v1 = src[2 * i + 1];
            uint4 o;
            o.x = f16x2(v0.y, v0.x);
            o.y = f16x2(v0.w, v0.z);
            o.z = f16x2(v1.y, v1.x);
            o.w = f16x2(v1.w, v1.z);
            dst[i] = o;
        }
    } else {
        // kern: pair fp16 words  g_kern_pair[r][p][u] = {k=2p+1, k=2p}
        const int total = NR * 32 * 64;            // 16384
        for (int i = (blockIdx.x - 2048) * blockDim.x + threadIdx.x; i < total;
             i += 8 * blockDim.x) {
            const int u = i & 63, p = (i >> 6) & 31, r = i >> 11;
            float f0 = kern[(r * 64 + 2 * p)     * NU + u];
            float f1 = kern[(r * 64 + 2 * p + 1) * NU + u];
            g_kern_pair[i] = f16x2(f1, f0);
        }
    }
}

// ---------------- main kernel ----------------
__global__ void __launch_bounds__(NTHREADS, 2)
graphconv_main(const int* __restrict__ mapping,
               const float* __restrict__ bias,
               float* __restrict__ out)
{
    extern __shared__ char smem[];
    const unsigned smem_u = cvta_smem(smem);

    const int tid  = threadIdx.x;
    const int row0 = blockIdx.x * ROWS;
    const int wid  = tid >> 5;
    const int l    = tid & 31;
    const int mg   = wid & 3;            // m-group: rows mg*32..+31
    const int ng   = wid >> 2;           // n-group: u ng*16..+15

    // gather roles: 4 lanes per row, 2 x 16B chunks each
    const int gm   = tid >> 2;           // local row 0..127
    const int gl   = tid & 3;
    const int grow = row0 + gm;
    const int bV   = (grow / NV) * NV;

    float d[2][2][4];
#pragma unroll
    for (int mt = 0; mt < 2; ++mt)
#pragma unroll
        for (int nt = 0; nt < 2; ++nt)
#pragma unroll
            for (int q = 0; q < 4; ++q) d[mt][nt][q] = 0.f;

    // ---- prologue: stage region 0 ----
    int m_cur = __ldg(mapping + (size_t)grow * NR);
    {
        const int srow = (m_cur >= 0) ? (bV + m_cur) : NROWS_TOT;
        const char* src = (const char*)(g_nodes_h + (size_t)srow * NC);
        unsigned dA = smem_u + OFF_A + (unsigned)(gm * 128);
#pragma unroll
        for (int j = 0; j < 2; ++j) {
            const int jj = gl * 2 + j;
            cpasync16(dA + (unsigned)((jj ^ (gm & 7)) << 4), src + jj * 16);
        }
        // B: 512 chunks of 16B, one per thread
        {
            const int p = tid >> 4, ch = tid & 15;
            cpasync16(smem_u + OFF_B + (unsigned)(p * 288 + ch * 16),
                      (const char*)g_kern_pair + (p * 64 + ch * 4) * 4);
        }
        CP_COMMIT();
    }
    int m_nxt = __ldg(mapping + (size_t)grow * NR + 1);

#pragma unroll 1
    for (int r = 0; r < NR; ++r) {
        const int buf = r & 1;

        // ---- stage region r+1 into the other buffer ----
        if (r < NR - 1) {
            const int nb = buf ^ 1;
            const int srow = (m_nxt >= 0) ? (bV + m_nxt) : NROWS_TOT;
            const char* src = (const char*)(g_nodes_h + (size_t)srow * NC);
            unsigned dA = smem_u + OFF_A + (unsigned)(nb * A_BUF + gm * 128);
#pragma unroll
            for (int j = 0; j < 2; ++j) {
                const int jj = gl * 2 + j;
                cpasync16(dA + (unsigned)((jj ^ (gm & 7)) << 4), src + jj * 16);
            }
            const char* kg = (const char*)g_kern_pair + (r + 1) * 2048 * 4;
            {
                const int p = tid >> 4, ch = tid & 15;
                cpasync16(smem_u + OFF_B + (unsigned)(nb * B_BUF + p * 288 + ch * 16),
                          kg + (p * 64 + ch * 4) * 4);
            }
            CP_COMMIT();
            if (r < NR - 2) m_nxt = __ldg(mapping + (size_t)grow * NR + r + 2);
        }

        if (r < NR - 1) { CP_WAIT(1); } else { CP_WAIT(0); }
        __syncthreads();

        // ---- compute: 4 k-steps of m16n8k16 fp16 ----
        const unsigned a_base = smem_u + OFF_A
            + (unsigned)(buf * A_BUF + (mg * 32 + (l & 15)) * 128);
        const int rx = l & 7;
        const char* Bh = smem + OFF_B + buf * B_BUF
            + (l & 3) * 288 + (ng * 16 + (l >> 2)) * 4;

#pragma unroll
        for (int ks = 0; ks < 4; ++ks) {
            unsigned b0[2], b1[2];
#pragma unroll
            for (int nt = 0; nt < 2; ++nt) {
                b0[nt] = *(const unsigned*)(Bh + (ks * 8)     * 288 + nt * 32);
                b1[nt] = *(const unsigned*)(Bh + (ks * 8 + 4) * 288 + nt * 32);
            }
#pragma unroll
            for (int mt = 0; mt < 2; ++mt) {
                unsigned a0, a1, a2, a3;
                ldsm_x4(a_base + (unsigned)(mt * 16 * 128)
                        + (unsigned)((((ks * 2 + (l >> 4)) ^ rx) << 4)),
                        a0, a1, a2, a3);
#pragma unroll
                for (int nt = 0; nt < 2; ++nt)
                    mma_f16(d[mt][nt][0], d[mt][nt][1], d[mt][nt][2], d[mt][nt][3],
                            a0, a1, a2, a3, b0[nt], b1[nt]);
            }
        }
        __syncthreads();   // done reading buf before refill
    }

    // ---- epilogue: bias + relu + STG.64 straight from fragments ----
#pragma unroll
    for (int nt = 0; nt < 2; ++nt) {
        const int u0 = ng * 16 + nt * 8 + 2 * (l & 3);
        float2 bv = *(const float2*)(bias + u0);
#pragma unroll
        for (int mt = 0; mt < 2; ++mt) {
            const int rA = row0 + mg * 32 + mt * 16 + (l >> 2);
            float2 o0, o1;
            o0.x = fmaxf(d[mt][nt][0] + bv.x, 0.f);
            o0.y = fmaxf(d[mt][nt][1] + bv.y, 0.f);
            o1.x = fmaxf(d[mt][nt][2] + bv.x, 0.f);
            o1.y = fmaxf(d[mt][nt][3] + bv.y, 0.f);
            *(float2*)(out + (size_t)rA * NU + u0)       = o0;
            *(float2*)(out + (size_t)(rA + 8) * NU + u0) = o1;
        }
    }
}

extern "C" void kernel_launch(void* const* d_in, const int* in_sizes, int n_in,
                              void* d_out, int out_size) {
    (void)in_sizes; (void)n_in; (void)out_size;
    const float* nodes   = (const float*)d_in[0];
    const int*   mapping = (const int*)d_in[1];
    const float* kern    = (const float*)d_in[2];
    const float* bias    = (const float*)d_in[3];
    float*       out     = (float*)d_out;

    conv_all<<<2056, 256>>>(nodes, kern);

    cudaFuncSetAttribute(graphconv_main,
                         cudaFuncAttributeMaxDynamicSharedMemorySize, SMEM_BYTES);
    int grid = NROWS_TOT / ROWS;   // 1250
    graphconv_main<<<grid, NTHREADS, SMEM_BYTES>>>(mapping, bias, out);
}